// round 2
// baseline (speedup 1.0000x reference)
#include <cuda_runtime.h>
#include <cstdint>

#define NROWS 131072
#define HALFN 65536
#define DDIM  512
#define HDIM  512
#define EPTN  65536

// Scratch for w2f = X @ W2[t] + b2[t]  (131072 x 512 f32 = 256 MiB)
__device__ float g_w2f[(size_t)NROWS * HDIM];

constexpr int BM = 128, BN = 128, BK = 16;

// One GEMM body, two epilogues:
//  EDGE=false: C[ry..][cx..] = A @ W[t] + b[t], t = row-half (proj kernels)
//  EDGE=true : per edge-row e: atomicAdd(out[src_e], acc + b5 + w2f[dst_e])
template<bool EDGE>
__global__ __launch_bounds__(256, 2)
void hetero_gemm_kernel(const float* __restrict__ A,
                        const float* __restrict__ W,
                        const float* __restrict__ bias,
                        float* __restrict__ C,
                        const int* __restrict__ edges,   // int32 pairs (src,dst)
                        float* __restrict__ out)
{
    __shared__ float As[BK][BM + 4];   // +4 pad: kills store bank conflicts
    __shared__ float Bs[BK][BN];

    const int ry = blockIdx.y * BM;
    const int cx = blockIdx.x * BN;

    int t = 0;
    if (!EDGE) t = (ry >= HALFN) ? 1 : 0;   // 65536 % 128 == 0 -> uniform per block
    const float* Wt = W + (size_t)t * DDIM * HDIM;
    const float* bt = bias + t * HDIM;

    const int tid  = threadIdx.x;
    const int tx   = tid & 15;
    const int ty   = tid >> 4;

    // global->smem load mapping
    const int arow = tid >> 2;          // 0..63
    const int acol = (tid & 3) << 2;    // 0,4,8,12
    const int brow = tid >> 5;          // 0..7
    const int bcol = (tid & 31) << 2;   // 0..124

    const float* Ag0 = A + (size_t)(ry + arow) * DDIM + acol;
    const float* Ag1 = Ag0 + (size_t)64 * DDIM;
    const float* Bg0 = Wt + (size_t)brow * HDIM + cx + bcol;
    const float* Bg1 = Bg0 + (size_t)8 * HDIM;

    float acc[8][8];
    #pragma unroll
    for (int i = 0; i < 8; i++)
        #pragma unroll
        for (int j = 0; j < 8; j++) acc[i][j] = 0.f;

    for (int k0 = 0; k0 < DDIM; k0 += BK) {
        const float4 a0 = *(const float4*)(Ag0 + k0);
        const float4 a1 = *(const float4*)(Ag1 + k0);
        const float4 b0 = *(const float4*)(Bg0 + (size_t)k0 * HDIM);
        const float4 b1 = *(const float4*)(Bg1 + (size_t)k0 * HDIM);
        __syncthreads();
        As[acol + 0][arow]      = a0.x; As[acol + 1][arow]      = a0.y;
        As[acol + 2][arow]      = a0.z; As[acol + 3][arow]      = a0.w;
        As[acol + 0][arow + 64] = a1.x; As[acol + 1][arow + 64] = a1.y;
        As[acol + 2][arow + 64] = a1.z; As[acol + 3][arow + 64] = a1.w;
        *(float4*)&Bs[brow    ][bcol] = b0;
        *(float4*)&Bs[brow + 8][bcol] = b1;
        __syncthreads();
        #pragma unroll
        for (int k = 0; k < BK; ++k) {
            const float4 af0 = *(const float4*)&As[k][ty * 8];
            const float4 af1 = *(const float4*)&As[k][ty * 8 + 4];
            const float4 bf0 = *(const float4*)&Bs[k][tx * 8];
            const float4 bf1 = *(const float4*)&Bs[k][tx * 8 + 4];
            const float a[8] = {af0.x, af0.y, af0.z, af0.w, af1.x, af1.y, af1.z, af1.w};
            const float b[8] = {bf0.x, bf0.y, bf0.z, bf0.w, bf1.x, bf1.y, bf1.z, bf1.w};
            #pragma unroll
            for (int i = 0; i < 8; i++)
                #pragma unroll
                for (int j = 0; j < 8; j++)
                    acc[i][j] = fmaf(a[i], b[j], acc[i][j]);
        }
    }

    const int col0 = cx + tx * 8;
    float bregs[8];
    #pragma unroll
    for (int j = 0; j < 8; j++) bregs[j] = bt[col0 + j];

    if (!EDGE) {
        #pragma unroll
        for (int i = 0; i < 8; i++) {
            const int r = ry + ty * 8 + i;
            const float4 v0 = make_float4(acc[i][0] + bregs[0], acc[i][1] + bregs[1],
                                          acc[i][2] + bregs[2], acc[i][3] + bregs[3]);
            const float4 v1 = make_float4(acc[i][4] + bregs[4], acc[i][5] + bregs[5],
                                          acc[i][6] + bregs[6], acc[i][7] + bregs[7]);
            *(float4*)(C + (size_t)r * HDIM + col0)     = v0;
            *(float4*)(C + (size_t)r * HDIM + col0 + 4) = v1;
        }
    } else {
        #pragma unroll
        for (int i = 0; i < 8; i++) {
            const int e = ry + ty * 8 + i;
            const int2 ed = *(const int2*)(edges + 2 * (size_t)e);  // int32 (src,dst)
            const int src = ed.x;
            const int dst = ed.y;
            // half-warp (same edge row) covers 512B contiguous -> coalesced
            const float4 w20 = *(const float4*)(g_w2f + (size_t)dst * HDIM + col0);
            const float4 w21 = *(const float4*)(g_w2f + (size_t)dst * HDIM + col0 + 4);
            float* op = out + (size_t)src * HDIM + col0;
            atomicAdd(op + 0, acc[i][0] + bregs[0] + w20.x);
            atomicAdd(op + 1, acc[i][1] + bregs[1] + w20.y);
            atomicAdd(op + 2, acc[i][2] + bregs[2] + w20.z);
            atomicAdd(op + 3, acc[i][3] + bregs[3] + w20.w);
            atomicAdd(op + 4, acc[i][4] + bregs[4] + w21.x);
            atomicAdd(op + 5, acc[i][5] + bregs[5] + w21.y);
            atomicAdd(op + 6, acc[i][6] + bregs[6] + w21.z);
            atomicAdd(op + 7, acc[i][7] + bregs[7] + w21.w);
        }
    }
}

extern "C" void kernel_launch(void* const* d_in, const int* in_sizes, int n_in,
                              void* d_out, int out_size)
{
    // metadata order: X E0 E1 W1 b1 W2 b2 W3 b3 W4 b4 W5 b5 edges0 edges1
    const float* X  = (const float*)d_in[0];
    const float* E0 = (const float*)d_in[1];
    const float* E1 = (const float*)d_in[2];
    const float* W1 = (const float*)d_in[3];
    const float* b1 = (const float*)d_in[4];
    const float* W2 = (const float*)d_in[5];
    const float* b2 = (const float*)d_in[6];
    // W3/b3/W4/b4 are dead: softmax over a singleton axis is identically 1.
    const float* W5 = (const float*)d_in[11];
    const float* b5 = (const float*)d_in[12];
    // JAX default config aliases int64 -> int32: edges are int32 pairs.
    const int* edges0 = (const int*)d_in[13];
    const int* edges1 = (const int*)d_in[14];
    float* out = (float*)d_out;

    float* w2f = nullptr;
    cudaGetSymbolAddress((void**)&w2f, g_w2f);   // no alloc; capture-safe

    dim3 blk(256);
    dim3 gproj(HDIM / BN, NROWS / BM);   // (4, 1024)
    dim3 gedge(HDIM / BN, EPTN / BM);    // (4, 512)

    // out = X @ W1[t] + b1[t]   (fully initializes d_out)
    hetero_gemm_kernel<false><<<gproj, blk>>>(X, W1, b1, out, nullptr, nullptr);
    // w2f = X @ W2[t] + b2[t]
    hetero_gemm_kernel<false><<<gproj, blk>>>(X, W2, b2, w2f, nullptr, nullptr);
    // t=0: out[src] += (E0 @ W5[0] + b5[0]) + w2f[dst]
    hetero_gemm_kernel<true><<<gedge, blk>>>(E0, W5, b5, nullptr, edges0, out);
    // t=1: out[src] += (E1 @ W5[1] + b5[1]) + w2f[dst]
    hetero_gemm_kernel<true><<<gedge, blk>>>(E1, W5 + (size_t)DDIM * HDIM, b5 + HDIM,
                                             nullptr, edges1, out);
}